// round 11
// baseline (speedup 1.0000x reference)
#include <cuda_runtime.h>

#define BATCH 64
#define TLEN 512
#define HDIM 768
#define NLAB 9
#define START_ID 7
#define NEG_INF_F (-10000.0f)

// Scratch for features [B, T, L]
__device__ float g_feats[BATCH * TLEN * NLAB];

// ---------------------------------------------------------------------------
// Kernel A: feats = hidden_states @ W + b
// grid=256 (single wave at 3 blocks/SM), each warp-slot does exactly 4 quads
// (16 rows) in a loop; Wt loaded once per block. Scalar FMA (FFMA2 was
// neutral). Reduction uses a dedicated scratch so Wt survives across quads.
// ---------------------------------------------------------------------------
__global__ void __launch_bounds__(256, 3) feats_kernel(
    const float* __restrict__ hs,     // [B*T, H]
    const float* __restrict__ W,      // [H, L]
    const float* __restrict__ bias)   // [L]
{
    __shared__ float Wt[NLAB * HDIM];    // 27648 B, live for whole kernel
    __shared__ float red[8][648];        // 20736 B per-warp reduction scratch

    int tid = threadIdx.x;
    for (int i = tid; i < HDIM * NLAB; i += blockDim.x) {
        int h = i / NLAB;
        int l = i - h * NLAB;
        Wt[l * HDIM + h] = W[i];
    }
    __syncthreads();

    int lane = tid & 31;
    int warp = tid >> 5;
    int ws = blockIdx.x * 8 + warp;      // warp-slot 0..2047

    const float4* WT4 = (const float4*)Wt;
    float* myred = red[warp];

#pragma unroll 1
    for (int j8 = 0; j8 < 4; j8++) {
        int row0 = ws * 16 + j8 * 4;     // 2048 slots * 16 rows = 32768

        float acc[4][NLAB];
#pragma unroll
        for (int r = 0; r < 4; r++)
#pragma unroll
            for (int l = 0; l < NLAB; l++) acc[r][l] = 0.0f;

#pragma unroll
        for (int k = 0; k < 6; k++) {
            int j = k * 32 + lane;
            float4 x[4];
#pragma unroll
            for (int r = 0; r < 4; r++)
                x[r] = ((const float4*)(hs + (row0 + r) * HDIM))[j];
#pragma unroll
            for (int l = 0; l < NLAB; l++) {
                float4 w = WT4[l * 192 + j];
#pragma unroll
                for (int r = 0; r < 4; r++)
                    acc[r][l] += x[r].x * w.x + x[r].y * w.y + x[r].z * w.z + x[r].w * w.w;
            }
        }

        // Cross-lane reduction via per-warp SMEM transpose
#pragma unroll
        for (int half = 0; half < 2; half++) {
#pragma unroll
            for (int p = 0; p < 18; p++) {
                int r = half * 2 + (p >= 9 ? 1 : 0);
                int l = (p >= 9) ? p - 9 : p;
                myred[p * 36 + lane] = acc[r][l];
            }
            __syncwarp();
            if (lane < 18) {
                const float4* q = (const float4*)(myred + lane * 36);
                float4 a = q[0], b2 = q[1], c2 = q[2], d2 = q[3];
                float4 e2 = q[4], f2 = q[5], g2 = q[6], h2 = q[7];
                float s0 = (a.x + a.y) + (a.z + a.w);
                float s1 = (b2.x + b2.y) + (b2.z + b2.w);
                float s2 = (c2.x + c2.y) + (c2.z + c2.w);
                float s3 = (d2.x + d2.y) + (d2.z + d2.w);
                float s4 = (e2.x + e2.y) + (e2.z + e2.w);
                float s5 = (f2.x + f2.y) + (f2.z + f2.w);
                float s6 = (g2.x + g2.y) + (g2.z + g2.w);
                float s7 = (h2.x + h2.y) + (h2.z + h2.w);
                float sum = ((s0 + s1) + (s2 + s3)) + ((s4 + s5) + (s6 + s7));
                int r = half * 2 + (lane >= 9 ? 1 : 0);
                int l = (lane >= 9) ? lane - 9 : lane;
                g_feats[(row0 + r) * NLAB + l] = sum + bias[l];
            }
            __syncwarp();
        }
    }
}

// ---------------------------------------------------------------------------
// Kernel B: Viterbi, one warp per batch. Forward loop stores only deltas
// (dlog); backpointers recomputed exactly from dlog during the parallel
// chunked backtrack (no psi in the serial loop).
// ---------------------------------------------------------------------------
__global__ void __launch_bounds__(32) viterbi_kernel(
    const float* __restrict__ trans,  // [L, L], trans[to*L + from]
    float* __restrict__ out)          // [B, T] float32
{
    __shared__ float sfeats[TLEN * NLAB + 16];   // +pad for prefetch
    __shared__ float dlog[TLEN * NLAB];          // d_t rows, t = 0..511
    __shared__ float strans[NLAB * NLAB];

    // path overlays sfeats (dead after forward pass): 16*9*32 = 4608 B
    unsigned char* path = (unsigned char*)sfeats;

    int b = blockIdx.x;
    int lane = threadIdx.x;
    int myl = lane < NLAB ? lane : 0;

    // Stage feats (coalesced float4)
    {
        const float4* src = (const float4*)(g_feats + b * TLEN * NLAB);
        float4* dst = (float4*)sfeats;
#pragma unroll
        for (int i = 0; i < 36; i++)
            dst[i * 32 + lane] = src[i * 32 + lane];
    }

    float tr[8];
#pragma unroll
    for (int f = 0; f < 8; f++) tr[f] = trans[myl * NLAB + f];
    for (int i = lane; i < NLAB * NLAB; i += 32)
        strans[i] = trans[i];

    __syncwarp();

    float d = (lane == START_ID) ? 0.0f : NEG_INF_F;
    if (lane < NLAB) dlog[lane] = d;
    float feat = sfeats[1 * NLAB + myl];

    for (int t = 1; t < TLEN; t++) {
        float feat_next = sfeats[(t + 1) * NLAB + myl];

        float s[8], v[8];
#pragma unroll
        for (int f = 0; f < 8; f++) s[f] = __shfl_sync(0xffffffffu, d, f);
#pragma unroll
        for (int f = 0; f < 8; f++) v[f] = tr[f] + s[f];

        float m01 = fmaxf(v[0], v[1]);
        float m23 = fmaxf(v[2], v[3]);
        float m45 = fmaxf(v[4], v[5]);
        float m67 = fmaxf(v[6], v[7]);
        float m07 = fmaxf(fmaxf(m01, m23), fmaxf(m45, m67));

        d = m07 + feat;
        if (lane < NLAB) dlog[t * NLAB + lane] = d;

        feat = feat_next;
    }

    __syncwarp();

    // Final argmax over 9 states (first-index ties), replicated in all lanes
    float fin[NLAB];
#pragma unroll
    for (int f = 0; f < NLAB; f++) fin[f] = __shfl_sync(0xffffffffu, d, f);
    float best = fin[0];
    int last = 0;
#pragma unroll
    for (int f = 1; f < NLAB; f++)
        if (fin[f] > best) { best = fin[f]; last = f; }

    // Phase B1: 144 backtrack tasks; argmax recomputed exactly from dlog.
    // s_t = argmax_f( trans[s_{t+1}][f] + d_t[f] ), f in 0..7 (f=8 never wins).
#pragma unroll
    for (int round = 0; round < 5; round++) {
        int task = round * 32 + lane;
        if (task < 16 * NLAB) {
            int c = task / NLAB;
            int x = task - c * NLAB;
            int lo = c * 32;
            int hi = (c == 15) ? 510 : lo + 31;
            int p = x;
            unsigned char* pc = &path[(c * NLAB + x) * 32];
            for (int t = hi; t >= lo; t--) {
                const float* dl = dlog + t * NLAB;
                const float* tp = strans + p * NLAB;
                float v0 = tp[0] + dl[0], v1 = tp[1] + dl[1];
                float v2 = tp[2] + dl[2], v3 = tp[3] + dl[3];
                float v4 = tp[4] + dl[4], v5 = tp[5] + dl[5];
                float v6 = tp[6] + dl[6], v7 = tp[7] + dl[7];
                float m01 = fmaxf(v0, v1);  int i01 = (v0 >= v1) ? 0 : 1;
                float m23 = fmaxf(v2, v3);  int i23 = (v2 >= v3) ? 2 : 3;
                float m45 = fmaxf(v4, v5);  int i45 = (v4 >= v5) ? 4 : 5;
                float m67 = fmaxf(v6, v7);  int i67 = (v6 >= v7) ? 6 : 7;
                float m03 = fmaxf(m01, m23); int i03 = (m01 >= m23) ? i01 : i23;
                float m47 = fmaxf(m45, m67); int i47 = (m45 >= m67) ? i45 : i67;
                p = (m03 >= m47) ? i03 : i47;
                pc[t - lo] = (unsigned char)p;
            }
        }
    }
    __syncwarp();

    // Phase B2: compose chunk exit states (15-deep chain, replicated)
    int X[16];
    X[15] = last;
#pragma unroll
    for (int c = 15; c > 0; c--)
        X[c - 1] = path[(c * NLAB + X[c]) * 32];

    // Phase B3: parallel output fill
    float* ob = out + b * TLEN;
#pragma unroll
    for (int i = 0; i < 16; i++) {
        int t = i * 32 + lane;
        int lbl = path[(i * NLAB + X[i]) * 32 + lane];
        if (t == TLEN - 1) lbl = last;
        ob[t] = (float)lbl;
    }
}

// ---------------------------------------------------------------------------
extern "C" void kernel_launch(void* const* d_in, const int* in_sizes, int n_in,
                              void* d_out, int out_size)
{
    const float* hidden = nullptr;
    const float* W      = nullptr;
    const float* bias   = nullptr;
    const float* trans  = nullptr;

    for (int i = 0; i < n_in; i++) {
        switch (in_sizes[i]) {
            case BATCH * TLEN * HDIM: hidden = (const float*)d_in[i]; break;
            case HDIM * NLAB:         W      = (const float*)d_in[i]; break;
            case NLAB:                bias   = (const float*)d_in[i]; break;
            case NLAB * NLAB:         trans  = (const float*)d_in[i]; break;
            default: break;
        }
    }

    float* out = (float*)d_out;

    feats_kernel<<<256, 256>>>(hidden, W, bias);
    viterbi_kernel<<<BATCH, 32>>>(trans, out);
}

// round 12
// speedup vs baseline: 1.1333x; 1.1333x over previous
#include <cuda_runtime.h>

#define BATCH 64
#define TLEN 512
#define HDIM 768
#define NLAB 9
#define START_ID 7
#define NEG_INF_F (-10000.0f)

#define GRIDA 444          // 148 SMs * 3 blocks/SM: one even wave
#define NUNITS 1024        // 32768 rows / 32 rows per block-unit

// Scratch for features [B, T, L]
__device__ float g_feats[BATCH * TLEN * NLAB];

// ---------------------------------------------------------------------------
// Kernel A: feats = hidden_states @ W + b
// grid=444 = exactly 3 blocks on every SM (even single wave, 24 warps/SM for
// DRAM latency hiding). Block-strided loop over 1024 units of 32 rows.
// ---------------------------------------------------------------------------
__global__ void __launch_bounds__(256, 3) feats_kernel(
    const float* __restrict__ hs,     // [B*T, H]
    const float* __restrict__ W,      // [H, L]
    const float* __restrict__ bias)   // [L]
{
    __shared__ float Wt[NLAB * HDIM];    // 27648 B, live for whole kernel
    __shared__ float red[8][648];        // 20736 B per-warp reduction scratch

    int tid = threadIdx.x;
    for (int i = tid; i < HDIM * NLAB; i += blockDim.x) {
        int h = i / NLAB;
        int l = i - h * NLAB;
        Wt[l * HDIM + h] = W[i];
    }
    __syncthreads();

    int lane = tid & 31;
    int warp = tid >> 5;

    const float4* WT4 = (const float4*)Wt;
    float* myred = red[warp];

#pragma unroll 1
    for (int u = blockIdx.x; u < NUNITS; u += GRIDA) {
        int row0 = u * 32 + warp * 4;

        float acc[4][NLAB];
#pragma unroll
        for (int r = 0; r < 4; r++)
#pragma unroll
            for (int l = 0; l < NLAB; l++) acc[r][l] = 0.0f;

#pragma unroll
        for (int k = 0; k < 6; k++) {
            int j = k * 32 + lane;
            float4 x[4];
#pragma unroll
            for (int r = 0; r < 4; r++)
                x[r] = ((const float4*)(hs + (row0 + r) * HDIM))[j];
#pragma unroll
            for (int l = 0; l < NLAB; l++) {
                float4 w = WT4[l * 192 + j];
#pragma unroll
                for (int r = 0; r < 4; r++)
                    acc[r][l] += x[r].x * w.x + x[r].y * w.y + x[r].z * w.z + x[r].w * w.w;
            }
        }

        // Cross-lane reduction via per-warp SMEM transpose
#pragma unroll
        for (int half = 0; half < 2; half++) {
#pragma unroll
            for (int p = 0; p < 18; p++) {
                int r = half * 2 + (p >= 9 ? 1 : 0);
                int l = (p >= 9) ? p - 9 : p;
                myred[p * 36 + lane] = acc[r][l];
            }
            __syncwarp();
            if (lane < 18) {
                const float4* q = (const float4*)(myred + lane * 36);
                float4 a = q[0], b2 = q[1], c2 = q[2], d2 = q[3];
                float4 e2 = q[4], f2 = q[5], g2 = q[6], h2 = q[7];
                float s0 = (a.x + a.y) + (a.z + a.w);
                float s1 = (b2.x + b2.y) + (b2.z + b2.w);
                float s2 = (c2.x + c2.y) + (c2.z + c2.w);
                float s3 = (d2.x + d2.y) + (d2.z + d2.w);
                float s4 = (e2.x + e2.y) + (e2.z + e2.w);
                float s5 = (f2.x + f2.y) + (f2.z + f2.w);
                float s6 = (g2.x + g2.y) + (g2.z + g2.w);
                float s7 = (h2.x + h2.y) + (h2.z + h2.w);
                float sum = ((s0 + s1) + (s2 + s3)) + ((s4 + s5) + (s6 + s7));
                int r = half * 2 + (lane >= 9 ? 1 : 0);
                int l = (lane >= 9) ? lane - 9 : lane;
                g_feats[(row0 + r) * NLAB + l] = sum + bias[l];
            }
            __syncwarp();
        }
    }
}

// ---------------------------------------------------------------------------
// Kernel B: Viterbi (proven Round-7 version). One warp per batch element.
// psi in forward loop (off critical path); chunk-parallel backtrack.
// ---------------------------------------------------------------------------
__global__ void __launch_bounds__(32) viterbi_kernel(
    const float* __restrict__ trans,  // [L, L], trans[to*L + from]
    float* __restrict__ out)          // [B, T] float32
{
    __shared__ float sfeats[TLEN * NLAB + NLAB];       // +pad row
    __shared__ unsigned char psi[(TLEN - 1) * NLAB];
    __shared__ unsigned char path[16 * NLAB * 32];

    int b = blockIdx.x;
    int lane = threadIdx.x;
    int myl = lane < NLAB ? lane : 0;

    {
        const float4* src = (const float4*)(g_feats + b * TLEN * NLAB);
        float4* dst = (float4*)sfeats;
#pragma unroll
        for (int i = 0; i < 36; i++)
            dst[i * 32 + lane] = src[i * 32 + lane];
    }

    float tr[8];
#pragma unroll
    for (int f = 0; f < 8; f++) tr[f] = trans[myl * NLAB + f];

    __syncwarp();

    float d = (lane == START_ID) ? 0.0f : NEG_INF_F;
    float feat = sfeats[1 * NLAB + myl];

    for (int t = 1; t < TLEN; t++) {
        float feat_next = sfeats[(t + 1) * NLAB + myl];

        float s[8], v[8];
#pragma unroll
        for (int f = 0; f < 8; f++) s[f] = __shfl_sync(0xffffffffu, d, f);
#pragma unroll
        for (int f = 0; f < 8; f++) v[f] = tr[f] + s[f];

        float m01 = fmaxf(v[0], v[1]);  int i01 = (v[0] >= v[1]) ? 0 : 1;
        float m23 = fmaxf(v[2], v[3]);  int i23 = (v[2] >= v[3]) ? 2 : 3;
        float m45 = fmaxf(v[4], v[5]);  int i45 = (v[4] >= v[5]) ? 4 : 5;
        float m67 = fmaxf(v[6], v[7]);  int i67 = (v[6] >= v[7]) ? 6 : 7;
        float m03 = fmaxf(m01, m23);    int i03 = (m01 >= m23) ? i01 : i23;
        float m47 = fmaxf(m45, m67);    int i47 = (m45 >= m67) ? i45 : i67;
        float m07 = fmaxf(m03, m47);

        d = m07 + feat;

        int bi = (m03 >= m47) ? i03 : i47;
        if (lane < NLAB) psi[(t - 1) * NLAB + lane] = (unsigned char)bi;

        feat = feat_next;
    }

    __syncwarp();

    float fin[NLAB];
#pragma unroll
    for (int f = 0; f < NLAB; f++) fin[f] = __shfl_sync(0xffffffffu, d, f);
    float best = fin[0];
    int last = 0;
#pragma unroll
    for (int f = 1; f < NLAB; f++)
        if (fin[f] > best) { best = fin[f]; last = f; }

    // Phase B1: 144 backtrack tasks (16 chunks x 9 exits)
#pragma unroll
    for (int round = 0; round < 5; round++) {
        int task = round * 32 + lane;
        if (task < 16 * NLAB) {
            int c = task / NLAB;
            int x = task - c * NLAB;
            int lo = c * 32;
            int hi = (c == 15) ? 510 : lo + 31;
            int p = x;
            unsigned char* pc = &path[(c * NLAB + x) * 32];
            for (int t = hi; t >= lo; t--) {
                p = psi[t * NLAB + p];
                pc[t - lo] = (unsigned char)p;
            }
        }
    }
    __syncwarp();

    // Phase B2: compose chunk exit states
    int X[16];
    X[15] = last;
#pragma unroll
    for (int c = 15; c > 0; c--)
        X[c - 1] = path[(c * NLAB + X[c]) * 32];

    // Phase B3: parallel output fill
    float* ob = out + b * TLEN;
#pragma unroll
    for (int i = 0; i < 16; i++) {
        int t = i * 32 + lane;
        int lbl = path[(i * NLAB + X[i]) * 32 + lane];
        if (t == TLEN - 1) lbl = last;
        ob[t] = (float)lbl;
    }
}

// ---------------------------------------------------------------------------
extern "C" void kernel_launch(void* const* d_in, const int* in_sizes, int n_in,
                              void* d_out, int out_size)
{
    const float* hidden = nullptr;
    const float* W      = nullptr;
    const float* bias   = nullptr;
    const float* trans  = nullptr;

    for (int i = 0; i < n_in; i++) {
        switch (in_sizes[i]) {
            case BATCH * TLEN * HDIM: hidden = (const float*)d_in[i]; break;
            case HDIM * NLAB:         W      = (const float*)d_in[i]; break;
            case NLAB:                bias   = (const float*)d_in[i]; break;
            case NLAB * NLAB:         trans  = (const float*)d_in[i]; break;
            default: break;
        }
    }

    float* out = (float*)d_out;

    feats_kernel<<<GRIDA, 256>>>(hidden, W, bias);
    viterbi_kernel<<<BATCH, 32>>>(trans, out);
}

// round 13
// speedup vs baseline: 1.2048x; 1.0631x over previous
#include <cuda_runtime.h>

#define BATCH 64
#define TLEN 512
#define HDIM 768
#define NLAB 9
#define START_ID 7
#define NEG_INF_F (-10000.0f)

#define GRIDA 444          // 148 SMs * 3 blocks/SM: one even wave
#define NUNITS 1024        // 32768 rows / 32 rows per block-unit

// Scratch for features [B, T, L]
__device__ float g_feats[BATCH * TLEN * NLAB];

#define PACK_DUP_F32X2(out, v) \
    asm("mov.b64 %0, {%1, %1};" : "=l"(out) : "f"(v))
#define UNPACK_F32X2(lo, hi, in) \
    asm("mov.b64 {%0, %1}, %2;" : "=f"(lo), "=f"(hi) : "l"(in))
#define FMA_F32X2(d, a, b, c) \
    asm("fma.rn.f32x2 %0, %1, %2, %3;" : "=l"(d) : "l"(a), "l"(b), "l"(c))

// ---------------------------------------------------------------------------
// Kernel A: feats = hidden_states @ W + b
// W staged in smem PRE-PAIRED by label: Wp[lp][h] = (W[h][2lp], W[h][2lp+1])
// so LDS.128 yields ready 64-bit FFMA2 operands (zero w-pack instructions).
// Label 8 handled scalar. FFMA2 per-component rounding == FFMA, same order.
// ---------------------------------------------------------------------------
__global__ void __launch_bounds__(256, 3) feats_kernel(
    const float* __restrict__ hs,     // [B*T, H]
    const float* __restrict__ W,      // [H, L]
    const float* __restrict__ bias)   // [L]
{
    __shared__ float2 Wp[4 * HDIM];      // 24576 B: label pairs (0,1)..(6,7)
    __shared__ float  W8[HDIM];          //  3072 B: label 8
    __shared__ float  red[8][648];       // 20736 B reduction scratch (total 48384)

    int tid = threadIdx.x;
    for (int h = tid; h < HDIM; h += blockDim.x) {
        const float* wr = W + h * NLAB;
#pragma unroll
        for (int lp = 0; lp < 4; lp++)
            Wp[lp * HDIM + h] = make_float2(wr[2 * lp], wr[2 * lp + 1]);
        W8[h] = wr[8];
    }
    __syncthreads();

    int lane = tid & 31;
    int warp = tid >> 5;
    float* myred = red[warp];

#pragma unroll 1
    for (int u = blockIdx.x; u < NUNITS; u += GRIDA) {
        int row0 = u * 32 + warp * 4;

        unsigned long long acc2[4][4];   // [row][label-pair]
        float acc8[4];
#pragma unroll
        for (int r = 0; r < 4; r++) {
#pragma unroll
            for (int lp = 0; lp < 4; lp++) acc2[r][lp] = 0ull;
            acc8[r] = 0.0f;
        }

#pragma unroll
        for (int k = 0; k < 6; k++) {
            int j = k * 32 + lane;                 // float4 index over h
            float4 x[4];
#pragma unroll
            for (int r = 0; r < 4; r++)
                x[r] = ((const float4*)(hs + (row0 + r) * HDIM))[j];

            // duplicate x components into 64-bit (v,v)
            unsigned long long xd[4][4];
#pragma unroll
            for (int r = 0; r < 4; r++) {
                PACK_DUP_F32X2(xd[r][0], x[r].x);
                PACK_DUP_F32X2(xd[r][1], x[r].y);
                PACK_DUP_F32X2(xd[r][2], x[r].z);
                PACK_DUP_F32X2(xd[r][3], x[r].w);
            }

#pragma unroll
            for (int lp = 0; lp < 4; lp++) {
                // two LDS.128: (h0,h1) and (h2,h3) label-pairs
                const ulonglong2* wp =
                    (const ulonglong2*)(Wp + lp * HDIM + 4 * j);
                ulonglong2 wa = wp[0];   // w[h0], w[h1]
                ulonglong2 wb = wp[1];   // w[h2], w[h3]
#pragma unroll
                for (int r = 0; r < 4; r++) {
                    FMA_F32X2(acc2[r][lp], xd[r][0], wa.x, acc2[r][lp]);
                    FMA_F32X2(acc2[r][lp], xd[r][1], wa.y, acc2[r][lp]);
                    FMA_F32X2(acc2[r][lp], xd[r][2], wb.x, acc2[r][lp]);
                    FMA_F32X2(acc2[r][lp], xd[r][3], wb.y, acc2[r][lp]);
                }
            }

            float4 w8 = ((const float4*)(W8))[j];
#pragma unroll
            for (int r = 0; r < 4; r++)
                acc8[r] += x[r].x * w8.x + x[r].y * w8.y
                         + x[r].z * w8.z + x[r].w * w8.w;
        }

        // Unpack to per-row, per-label accumulators
        float acc[4][NLAB];
#pragma unroll
        for (int r = 0; r < 4; r++) {
#pragma unroll
            for (int lp = 0; lp < 4; lp++)
                UNPACK_F32X2(acc[r][2 * lp], acc[r][2 * lp + 1], acc2[r][lp]);
            acc[r][8] = acc8[r];
        }

        // Cross-lane reduction via per-warp SMEM transpose
#pragma unroll
        for (int half = 0; half < 2; half++) {
#pragma unroll
            for (int p = 0; p < 18; p++) {
                int r = half * 2 + (p >= 9 ? 1 : 0);
                int l = (p >= 9) ? p - 9 : p;
                myred[p * 36 + lane] = acc[r][l];
            }
            __syncwarp();
            if (lane < 18) {
                const float4* q = (const float4*)(myred + lane * 36);
                float4 a = q[0], b2 = q[1], c2 = q[2], d2 = q[3];
                float4 e2 = q[4], f2 = q[5], g2 = q[6], h2 = q[7];
                float s0 = (a.x + a.y) + (a.z + a.w);
                float s1 = (b2.x + b2.y) + (b2.z + b2.w);
                float s2 = (c2.x + c2.y) + (c2.z + c2.w);
                float s3 = (d2.x + d2.y) + (d2.z + d2.w);
                float s4 = (e2.x + e2.y) + (e2.z + e2.w);
                float s5 = (f2.x + f2.y) + (f2.z + f2.w);
                float s6 = (g2.x + g2.y) + (g2.z + g2.w);
                float s7 = (h2.x + h2.y) + (h2.z + h2.w);
                float sum = ((s0 + s1) + (s2 + s3)) + ((s4 + s5) + (s6 + s7));
                int r = half * 2 + (lane >= 9 ? 1 : 0);
                int l = (lane >= 9) ? lane - 9 : lane;
                g_feats[(row0 + r) * NLAB + l] = sum + bias[l];
            }
            __syncwarp();
        }
    }
}

// ---------------------------------------------------------------------------
// Kernel B: Viterbi. psi rows padded to 32B -> unconditional store (no pred
// guard); t-loop unrolled 4x to amortize loop overhead and overlap tails.
// ---------------------------------------------------------------------------
__global__ void __launch_bounds__(32) viterbi_kernel(
    const float* __restrict__ trans,  // [L, L], trans[to*L + from]
    float* __restrict__ out)          // [B, T] float32
{
    __shared__ float sfeats[TLEN * NLAB + NLAB];       // 18468 B (+pad row)
    __shared__ unsigned char psi[(TLEN - 1) * 32];     // 16352 B, padded rows
    __shared__ unsigned char path[16 * NLAB * 32];     //  4608 B

    int b = blockIdx.x;
    int lane = threadIdx.x;
    int myl = lane < NLAB ? lane : 0;

    {
        const float4* src = (const float4*)(g_feats + b * TLEN * NLAB);
        float4* dst = (float4*)sfeats;
#pragma unroll
        for (int i = 0; i < 36; i++)
            dst[i * 32 + lane] = src[i * 32 + lane];
    }

    float tr[8];
#pragma unroll
    for (int f = 0; f < 8; f++) tr[f] = trans[myl * NLAB + f];

    __syncwarp();

    float d = (lane == START_ID) ? 0.0f : NEG_INF_F;
    float feat = sfeats[1 * NLAB + myl];

#pragma unroll 4
    for (int t = 1; t < TLEN; t++) {
        float feat_next = sfeats[(t + 1) * NLAB + myl];

        float s[8], v[8];
#pragma unroll
        for (int f = 0; f < 8; f++) s[f] = __shfl_sync(0xffffffffu, d, f);
#pragma unroll
        for (int f = 0; f < 8; f++) v[f] = tr[f] + s[f];

        float m01 = fmaxf(v[0], v[1]);  int i01 = (v[0] >= v[1]) ? 0 : 1;
        float m23 = fmaxf(v[2], v[3]);  int i23 = (v[2] >= v[3]) ? 2 : 3;
        float m45 = fmaxf(v[4], v[5]);  int i45 = (v[4] >= v[5]) ? 4 : 5;
        float m67 = fmaxf(v[6], v[7]);  int i67 = (v[6] >= v[7]) ? 6 : 7;
        float m03 = fmaxf(m01, m23);    int i03 = (m01 >= m23) ? i01 : i23;
        float m47 = fmaxf(m45, m67);    int i47 = (m45 >= m67) ? i45 : i67;
        float m07 = fmaxf(m03, m47);

        d = m07 + feat;

        int bi = (m03 >= m47) ? i03 : i47;
        psi[(t - 1) * 32 + lane] = (unsigned char)bi;   // lanes 9-31: pad

        feat = feat_next;
    }

    __syncwarp();

    float fin[NLAB];
#pragma unroll
    for (int f = 0; f < NLAB; f++) fin[f] = __shfl_sync(0xffffffffu, d, f);
    float best = fin[0];
    int last = 0;
#pragma unroll
    for (int f = 1; f < NLAB; f++)
        if (fin[f] > best) { best = fin[f]; last = f; }

    // Phase B1: 144 backtrack tasks (16 chunks x 9 exits)
#pragma unroll
    for (int round = 0; round < 5; round++) {
        int task = round * 32 + lane;
        if (task < 16 * NLAB) {
            int c = task / NLAB;
            int x = task - c * NLAB;
            int lo = c * 32;
            int hi = (c == 15) ? 510 : lo + 31;
            int p = x;
            unsigned char* pc = &path[(c * NLAB + x) * 32];
            for (int t = hi; t >= lo; t--) {
                p = psi[t * 32 + p];
                pc[t - lo] = (unsigned char)p;
            }
        }
    }
    __syncwarp();

    // Phase B2: compose chunk exit states
    int X[16];
    X[15] = last;
#pragma unroll
    for (int c = 15; c > 0; c--)
        X[c - 1] = path[(c * NLAB + X[c]) * 32];

    // Phase B3: parallel output fill
    float* ob = out + b * TLEN;
#pragma unroll
    for (int i = 0; i < 16; i++) {
        int t = i * 32 + lane;
        int lbl = path[(i * NLAB + X[i]) * 32 + lane];
        if (t == TLEN - 1) lbl = last;
        ob[t] = (float)lbl;
    }
}

// ---------------------------------------------------------------------------
extern "C" void kernel_launch(void* const* d_in, const int* in_sizes, int n_in,
                              void* d_out, int out_size)
{
    const float* hidden = nullptr;
    const float* W      = nullptr;
    const float* bias   = nullptr;
    const float* trans  = nullptr;

    for (int i = 0; i < n_in; i++) {
        switch (in_sizes[i]) {
            case BATCH * TLEN * HDIM: hidden = (const float*)d_in[i]; break;
            case HDIM * NLAB:         W      = (const float*)d_in[i]; break;
            case NLAB:                bias   = (const float*)d_in[i]; break;
            case NLAB * NLAB:         trans  = (const float*)d_in[i]; break;
            default: break;
        }
    }

    float* out = (float*)d_out;

    feats_kernel<<<GRIDA, 256>>>(hidden, W, bias);
    viterbi_kernel<<<BATCH, 32>>>(trans, out);
}

// round 16
// speedup vs baseline: 1.2526x; 1.0397x over previous
#include <cuda_runtime.h>

#define BATCH 64
#define TLEN 512
#define HDIM 768
#define NLAB 9
#define START_ID 7
#define NEG_INF_F (-10000.0f)

#define GRIDA 444          // 148 SMs * 3 blocks/SM: one even wave
#define NUNITS 1024        // 32768 rows / 32 rows per block-unit

// Scratch for features [B, T, L]
__device__ float g_feats[BATCH * TLEN * NLAB];

// ---------------------------------------------------------------------------
// Kernel A: feats = hidden_states @ W + b
// Scalar FMA + explicit double-buffered x prefetch to sustain ~8 LDG.128 in
// flight per warp (DRAM latency-hiding), __ldcs streaming loads.
// ---------------------------------------------------------------------------
__global__ void __launch_bounds__(256, 3) feats_kernel(
    const float* __restrict__ hs,     // [B*T, H]
    const float* __restrict__ W,      // [H, L]
    const float* __restrict__ bias)   // [L]
{
    __shared__ float Wt[NLAB * HDIM];    // 27648 B: [l][h]
    __shared__ float red[8][648];        // 20736 B reduction scratch

    int tid = threadIdx.x;
    for (int i = tid; i < HDIM * NLAB; i += blockDim.x) {
        int h = i / NLAB;
        int l = i - h * NLAB;
        Wt[l * HDIM + h] = W[i];
    }
    __syncthreads();

    int lane = tid & 31;
    int warp = tid >> 5;
    const float4* WT4 = (const float4*)Wt;
    float* myred = red[warp];

#pragma unroll 1
    for (int u = blockIdx.x; u < NUNITS; u += GRIDA) {
        int row0 = u * 32 + warp * 4;

        const float4* base0 = (const float4*)(hs + (row0 + 0) * HDIM);
        const float4* base1 = (const float4*)(hs + (row0 + 1) * HDIM);
        const float4* base2 = (const float4*)(hs + (row0 + 2) * HDIM);
        const float4* base3 = (const float4*)(hs + (row0 + 3) * HDIM);

        float acc[4][NLAB];
#pragma unroll
        for (int r = 0; r < 4; r++)
#pragma unroll
            for (int l = 0; l < NLAB; l++) acc[r][l] = 0.0f;

        // prefetch k=0
        float4 x0[4], x1[4];
        x0[0] = __ldcs(base0 + lane);
        x0[1] = __ldcs(base1 + lane);
        x0[2] = __ldcs(base2 + lane);
        x0[3] = __ldcs(base3 + lane);

#pragma unroll
        for (int k = 0; k < 6; k++) {
            // issue next k's loads BEFORE consuming current (keeps ~8 in flight)
            if (k < 5) {
                int jn = (k + 1) * 32 + lane;
                x1[0] = __ldcs(base0 + jn);
                x1[1] = __ldcs(base1 + jn);
                x1[2] = __ldcs(base2 + jn);
                x1[3] = __ldcs(base3 + jn);
            }

            int j = k * 32 + lane;
#pragma unroll
            for (int l = 0; l < NLAB; l++) {
                float4 w = WT4[l * 192 + j];
#pragma unroll
                for (int r = 0; r < 4; r++)
                    acc[r][l] += x0[r].x * w.x + x0[r].y * w.y
                               + x0[r].z * w.z + x0[r].w * w.w;
            }

#pragma unroll
            for (int r = 0; r < 4; r++) x0[r] = x1[r];
        }

        // Cross-lane reduction via per-warp SMEM transpose
#pragma unroll
        for (int half = 0; half < 2; half++) {
#pragma unroll
            for (int p = 0; p < 18; p++) {
                int r = half * 2 + (p >= 9 ? 1 : 0);
                int l = (p >= 9) ? p - 9 : p;
                myred[p * 36 + lane] = acc[r][l];
            }
            __syncwarp();
            if (lane < 18) {
                const float4* q = (const float4*)(myred + lane * 36);
                float4 a = q[0], b2 = q[1], c2 = q[2], d2 = q[3];
                float4 e2 = q[4], f2 = q[5], g2 = q[6], h2 = q[7];
                float s0 = (a.x + a.y) + (a.z + a.w);
                float s1 = (b2.x + b2.y) + (b2.z + b2.w);
                float s2 = (c2.x + c2.y) + (c2.z + c2.w);
                float s3 = (d2.x + d2.y) + (d2.z + d2.w);
                float s4 = (e2.x + e2.y) + (e2.z + e2.w);
                float s5 = (f2.x + f2.y) + (f2.z + f2.w);
                float s6 = (g2.x + g2.y) + (g2.z + g2.w);
                float s7 = (h2.x + h2.y) + (h2.z + h2.w);
                float sum = ((s0 + s1) + (s2 + s3)) + ((s4 + s5) + (s6 + s7));
                int r = half * 2 + (lane >= 9 ? 1 : 0);
                int l = (lane >= 9) ? lane - 9 : lane;
                g_feats[(row0 + r) * NLAB + l] = sum + bias[l];
            }
            __syncwarp();
        }
    }
}

// ---------------------------------------------------------------------------
// Kernel B: Viterbi (proven R13 version). psi rows padded to 32 B,
// unconditional store, 4x unroll; chunk-parallel backtrack.
// ---------------------------------------------------------------------------
__global__ void __launch_bounds__(32) viterbi_kernel(
    const float* __restrict__ trans,  // [L, L], trans[to*L + from]
    float* __restrict__ out)          // [B, T] float32
{
    __shared__ float sfeats[TLEN * NLAB + NLAB];       // 18468 B (+pad row)
    __shared__ unsigned char psi[(TLEN - 1) * 32];     // 16352 B, padded rows
    __shared__ unsigned char path[16 * NLAB * 32];     //  4608 B

    int b = blockIdx.x;
    int lane = threadIdx.x;
    int myl = lane < NLAB ? lane : 0;

    {
        const float4* src = (const float4*)(g_feats + b * TLEN * NLAB);
        float4* dst = (float4*)sfeats;
#pragma unroll
        for (int i = 0; i < 36; i++)
            dst[i * 32 + lane] = src[i * 32 + lane];
    }

    float tr[8];
#pragma unroll
    for (int f = 0; f < 8; f++) tr[f] = trans[myl * NLAB + f];

    __syncwarp();

    float d = (lane == START_ID) ? 0.0f : NEG_INF_F;
    float feat = sfeats[1 * NLAB + myl];

#pragma unroll 4
    for (int t = 1; t < TLEN; t++) {
        float feat_next = sfeats[(t + 1) * NLAB + myl];

        float s[8], v[8];
#pragma unroll
        for (int f = 0; f < 8; f++) s[f] = __shfl_sync(0xffffffffu, d, f);
#pragma unroll
        for (int f = 0; f < 8; f++) v[f] = tr[f] + s[f];

        float m01 = fmaxf(v[0], v[1]);  int i01 = (v[0] >= v[1]) ? 0 : 1;
        float m23 = fmaxf(v[2], v[3]);  int i23 = (v[2] >= v[3]) ? 2 : 3;
        float m45 = fmaxf(v[4], v[5]);  int i45 = (v[4] >= v[5]) ? 4 : 5;
        float m67 = fmaxf(v[6], v[7]);  int i67 = (v[6] >= v[7]) ? 6 : 7;
        float m03 = fmaxf(m01, m23);    int i03 = (m01 >= m23) ? i01 : i23;
        float m47 = fmaxf(m45, m67);    int i47 = (m45 >= m67) ? i45 : i67;
        float m07 = fmaxf(m03, m47);

        d = m07 + feat;

        int bi = (m03 >= m47) ? i03 : i47;
        psi[(t - 1) * 32 + lane] = (unsigned char)bi;   // lanes 9-31: pad

        feat = feat_next;
    }

    __syncwarp();

    float fin[NLAB];
#pragma unroll
    for (int f = 0; f < NLAB; f++) fin[f] = __shfl_sync(0xffffffffu, d, f);
    float best = fin[0];
    int last = 0;
#pragma unroll
    for (int f = 1; f < NLAB; f++)
        if (fin[f] > best) { best = fin[f]; last = f; }

    // Phase B1: 144 backtrack tasks (16 chunks x 9 exits)
#pragma unroll
    for (int round = 0; round < 5; round++) {
        int task = round * 32 + lane;
        if (task < 16 * NLAB) {
            int c = task / NLAB;
            int x = task - c * NLAB;
            int lo = c * 32;
            int hi = (c == 15) ? 510 : lo + 31;
            int p = x;
            unsigned char* pc = &path[(c * NLAB + x) * 32];
            for (int t = hi; t >= lo; t--) {
                p = psi[t * 32 + p];
                pc[t - lo] = (unsigned char)p;
            }
        }
    }
    __syncwarp();

    // Phase B2: compose chunk exit states
    int X[16];
    X[15] = last;
#pragma unroll
    for (int c = 15; c > 0; c--)
        X[c - 1] = path[(c * NLAB + X[c]) * 32];

    // Phase B3: parallel output fill
    float* ob = out + b * TLEN;
#pragma unroll
    for (int i = 0; i < 16; i++) {
        int t = i * 32 + lane;
        int lbl = path[(i * NLAB + X[i]) * 32 + lane];
        if (t == TLEN - 1) lbl = last;
        ob[t] = (float)lbl;
    }
}

// ---------------------------------------------------------------------------
extern "C" void kernel_launch(void* const* d_in, const int* in_sizes, int n_in,
                              void* d_out, int out_size)
{
    const float* hidden = nullptr;
    const float* W      = nullptr;
    const float* bias   = nullptr;
    const float* trans  = nullptr;

    for (int i = 0; i < n_in; i++) {
        switch (in_sizes[i]) {
            case BATCH * TLEN * HDIM: hidden = (const float*)d_in[i]; break;
            case HDIM * NLAB:         W      = (const float*)d_in[i]; break;
            case NLAB:                bias   = (const float*)d_in[i]; break;
            case NLAB * NLAB:         trans  = (const float*)d_in[i]; break;
            default: break;
        }
    }

    float* out = (float*)d_out;

    feats_kernel<<<GRIDA, 256>>>(hidden, W, bias);
    viterbi_kernel<<<BATCH, 32>>>(trans, out);
}